// round 3
// baseline (speedup 1.0000x reference)
#include <cuda_runtime.h>
#include <cuda_bf16.h>

// Problem constants (match reference_code)
#define NV     100000      // vertices
#define EFULL  3200000     // directed edges (rows = ei[0:E], cols = ei[E:2E])
#define E2     1600000     // EFULL/2
#define NB     8
#define NC     3
#define BC     24          // NB*NC real floats per vertex row
#define ROWP   32          // padded row stride (128 B)
#define NTOT   (NB*NV*NC)  // 2,400,000

// Scan config: 112*256*4 = 114688 >= NV
#define SCAN_B 112
#define SCAN_T 256
#define SCAN_K 4

#define GATHER_BLOCKS ((NV * 32 + 255) / 256)   // 12500, warp per vertex

// Scratch (static device globals; no allocation anywhere)
__device__ int   g_deg[NV];
__device__ int   g_rowptr[NV];
__device__ int   g_cur[NV];
__device__ int   g_bsum[SCAN_B];
__device__ int   g_adj[EFULL];
__device__ float g_dinv[NV];    // deg>0 ? deg^-1/2 : 0
__device__ float g_scale[NV];   // deg>0 ? deg^-1/2 : 1   (store-scale)
__device__ float g_rdeg[NV];    // deg>0 ? sqrt(deg) : 1  (recovery factor)
__device__ float g_dp[NV * ROWP];   // prescaled diff rows, 128B padded
__device__ float g_partial[GATHER_BLOCKS];
__device__ unsigned int g_done;

// ---------------------------------------------------------------------------
// K1: zero degree counters + done-counter
__global__ void k_init() {
    int i = blockIdx.x * blockDim.x + threadIdx.x;
    if (i < NV) g_deg[i] = 0;
    if (i == 0) g_done = 0u;
}

// K2: degree histogram, 4 edges per thread via int4
__global__ void k_deg(const int* __restrict__ ei) {
    int t = blockIdx.x * blockDim.x + threadIdx.x;
    if (t >= E2 / 4) return;
    int4 r = __ldg((const int4*)ei + t);            // src[4t..4t+3]
    int4 c = __ldg((const int4*)(ei + E2) + t);     // dst[4t..4t+3]
    atomicAdd(&g_deg[r.x], 1); atomicAdd(&g_deg[r.y], 1);
    atomicAdd(&g_deg[r.z], 1); atomicAdd(&g_deg[r.w], 1);
    atomicAdd(&g_deg[c.x], 1); atomicAdd(&g_deg[c.y], 1);
    atomicAdd(&g_deg[c.z], 1); atomicAdd(&g_deg[c.w], 1);
}

// K3a: per-block partial sums of degree
__global__ void k_scan_part() {
    int tid  = threadIdx.x;
    int base = blockIdx.x * (SCAN_T * SCAN_K) + tid * SCAN_K;
    int s = 0;
#pragma unroll
    for (int k = 0; k < SCAN_K; k++) {
        int i = base + k;
        if (i < NV) s += g_deg[i];
    }
    __shared__ int ws[SCAN_T / 32];
    for (int o = 16; o; o >>= 1) s += __shfl_down_sync(0xFFFFFFFFu, s, o);
    if ((tid & 31) == 0) ws[tid >> 5] = s;
    __syncthreads();
    if (tid < 32) {
        int v = (tid < SCAN_T / 32) ? ws[tid] : 0;
        for (int o = 4; o; o >>= 1) v += __shfl_down_sync(0xFFFFFFFFu, v, o);
        if (tid == 0) g_bsum[blockIdx.x] = v;
    }
}

// K3b: final scan. Each block computes its own lookback over the 112 block
// sums (cheap), then scans its tile: writes rowptr, cursor, dinv/scale/rdeg.
__global__ void k_scan_final() {
    int tid = threadIdx.x;

    // inline lookback: offset = sum of g_bsum[t] for t < blockIdx.x
    __shared__ int s_off;
    __shared__ int lw[SCAN_T / 32];
    {
        int v = (tid < blockIdx.x && tid < SCAN_B) ? g_bsum[tid] : 0;
        for (int o = 16; o; o >>= 1) v += __shfl_down_sync(0xFFFFFFFFu, v, o);
        if ((tid & 31) == 0) lw[tid >> 5] = v;
        __syncthreads();
        if (tid < 32) {
            int v2 = (tid < SCAN_T / 32) ? lw[tid] : 0;
            for (int o = 4; o; o >>= 1) v2 += __shfl_down_sync(0xFFFFFFFFu, v2, o);
            if (tid == 0) s_off = v2;
        }
        __syncthreads();
    }

    int base = blockIdx.x * (SCAN_T * SCAN_K) + tid * SCAN_K;
    int loc[SCAN_K];
    int s = 0;
#pragma unroll
    for (int k = 0; k < SCAN_K; k++) {
        int i = base + k;
        loc[k] = (i < NV) ? g_deg[i] : 0;
        s += loc[k];
    }
    int lane = tid & 31, w = tid >> 5;
    int x = s;
    for (int o = 1; o < 32; o <<= 1) {
        int t = __shfl_up_sync(0xFFFFFFFFu, x, o);
        if (lane >= o) x += t;
    }
    __shared__ int wt[SCAN_T / 32];
    __shared__ int wo[SCAN_T / 32];
    if (lane == 31) wt[w] = x;
    __syncthreads();
    if (tid == 0) {
        int a = 0;
        for (int k = 0; k < SCAN_T / 32; k++) { wo[k] = a; a += wt[k]; }
    }
    __syncthreads();
    int excl = x - s + wo[w] + s_off;
#pragma unroll
    for (int k = 0; k < SCAN_K; k++) {
        int i = base + k;
        if (i < NV) {
            g_rowptr[i] = excl;
            g_cur[i]    = excl;
            if (loc[k] > 0) {
                float di = rsqrtf((float)loc[k]);
                g_dinv[i]  = di;
                g_scale[i] = di;
                g_rdeg[i]  = sqrtf((float)loc[k]);
            } else {
                g_dinv[i]  = 0.0f;
                g_scale[i] = 1.0f;
                g_rdeg[i]  = 1.0f;
            }
            excl += loc[k];
        }
    }
}

// K4: CSR fill, 4 edges per thread via int4.
__global__ void k_fill(const int* __restrict__ ei) {
    int t = blockIdx.x * blockDim.x + threadIdx.x;
    if (t >= EFULL / 4) return;
    int4 r = __ldg((const int4*)ei + t);
    int4 c = __ldg((const int4*)(ei + EFULL) + t);
    g_adj[atomicAdd(&g_cur[r.x], 1)] = c.x;
    g_adj[atomicAdd(&g_cur[r.y], 1)] = c.y;
    g_adj[atomicAdd(&g_cur[r.z], 1)] = c.z;
    g_adj[atomicAdd(&g_cur[r.w], 1)] = c.w;
}

// K5: dp = scale_v * (x - y), transposed to (V, 32-padded) via smem staging.
// Block handles 32 vertices x 8 batches.
__global__ void k_diff(const float* __restrict__ x, const float* __restrict__ y) {
    __shared__ float sm[32 * 25];                 // row pad 25 to dodge conflicts
    __shared__ float ssc[32];
    int tid = threadIdx.x;                        // 256
    int v0  = blockIdx.x * 32;
    int b   = tid >> 5, vl = tid & 31;
    int bi  = b * (NV * NC) + (v0 + vl) * NC;
    float a0 = __ldg(x + bi + 0) - __ldg(y + bi + 0);
    float a1 = __ldg(x + bi + 1) - __ldg(y + bi + 1);
    float a2 = __ldg(x + bi + 2) - __ldg(y + bi + 2);
    if (tid < 32) ssc[tid] = __ldg(&g_scale[v0 + tid]);
    int so = vl * 25 + b * 3;
    sm[so + 0] = a0; sm[so + 1] = a1; sm[so + 2] = a2;
    __syncthreads();
    int gbase = v0 * ROWP;
#pragma unroll
    for (int k = 0; k < 3; k++) {
        int idx = tid * 3 + k;                    // 0..767, contiguous real floats
        int v = idx / BC, c = idx % BC;
        g_dp[gbase + v * ROWP + c] = ssc[v] * sm[v * 25 + c];
    }
}

// K6: fused gather + squared-error + final reduction (last-block-done).
// One warp per vertex: lanes 0..23 own the 24 real floats of the row.
__global__ void k_gather(float* __restrict__ out) {
    int gw   = (blockIdx.x * blockDim.x + threadIdx.x) >> 5;
    int lane = threadIdx.x & 31;
    float sq = 0.0f;
    if (gw < NV) {
        int start = __ldg(&g_rowptr[gw]);
        int deg   = __ldg(&g_deg[gw]);
        const int* ap = g_adj + start;
        float acc = 0.0f;
        int i = 0;
        for (; i + 8 <= deg; i += 8) {
            int u0 = __ldg(ap + i + 0), u1 = __ldg(ap + i + 1);
            int u2 = __ldg(ap + i + 2), u3 = __ldg(ap + i + 3);
            int u4 = __ldg(ap + i + 4), u5 = __ldg(ap + i + 5);
            int u6 = __ldg(ap + i + 6), u7 = __ldg(ap + i + 7);
            if (lane < BC) {
                float t0 = __ldg(g_dp + (u0 << 5) + lane);
                float t1 = __ldg(g_dp + (u1 << 5) + lane);
                float t2 = __ldg(g_dp + (u2 << 5) + lane);
                float t3 = __ldg(g_dp + (u3 << 5) + lane);
                float t4 = __ldg(g_dp + (u4 << 5) + lane);
                float t5 = __ldg(g_dp + (u5 << 5) + lane);
                float t6 = __ldg(g_dp + (u6 << 5) + lane);
                float t7 = __ldg(g_dp + (u7 << 5) + lane);
                acc += ((t0 + t1) + (t2 + t3)) + ((t4 + t5) + (t6 + t7));
            }
        }
        for (; i < deg; i++) {
            int u = __ldg(ap + i);
            if (lane < BC) acc += __ldg(g_dp + (u << 5) + lane);
        }
        if (lane < BC) {
            float val = __ldg(&g_rdeg[gw]) * __ldg(g_dp + (gw << 5) + lane)
                      - __ldg(&g_dinv[gw]) * acc;
            sq = val * val;
        }
    }
    // block reduce -> per-block partial
    for (int o = 16; o; o >>= 1) sq += __shfl_down_sync(0xFFFFFFFFu, sq, o);
    __shared__ float ws[8];
    __shared__ bool s_last;
    if (lane == 0) ws[threadIdx.x >> 5] = sq;
    __syncthreads();
    if (threadIdx.x == 0) {
        float v = 0.0f;
#pragma unroll
        for (int k = 0; k < 8; k++) v += ws[k];
        g_partial[blockIdx.x] = v;
        __threadfence();
        unsigned int done = atomicAdd(&g_done, 1u);
        s_last = (done == (unsigned int)(gridDim.x - 1));
    }
    __syncthreads();
    if (s_last) {
        // deterministic final sum by the last block
        float s = 0.0f;
        for (int i = threadIdx.x; i < GATHER_BLOCKS; i += blockDim.x)
            s += g_partial[i];
        for (int o = 16; o; o >>= 1) s += __shfl_down_sync(0xFFFFFFFFu, s, o);
        if (lane == 0) ws[threadIdx.x >> 5] = s;
        __syncthreads();
        if (threadIdx.x == 0) {
            float v = 0.0f;
#pragma unroll
            for (int k = 0; k < 8; k++) v += ws[k];
            out[0] = v * (1.0f / (float)NTOT);
        }
    }
}

// ---------------------------------------------------------------------------
extern "C" void kernel_launch(void* const* d_in, const int* in_sizes, int n_in,
                              void* d_out, int out_size) {
    const float* x  = (const float*)d_in[0];   // features      (B,V,C)
    const float* y  = (const float*)d_in[1];   // target_feats  (B,V,C)
    const int*   ei = (const int*)d_in[2];     // edge_index    (2,E)
    float* out = (float*)d_out;

    const int T = 256;
    k_init      <<<(NV + T - 1) / T, T>>>();
    k_deg       <<<(E2 / 4 + T - 1) / T, T>>>(ei);
    k_scan_part <<<SCAN_B, SCAN_T>>>();
    k_scan_final<<<SCAN_B, SCAN_T>>>();
    k_fill      <<<(EFULL / 4 + T - 1) / T, T>>>(ei);
    k_diff      <<<NV / 32, T>>>(x, y);
    k_gather    <<<GATHER_BLOCKS, T>>>(out);
}